// round 14
// baseline (speedup 1.0000x reference)
#include <cuda_runtime.h>
#include <math.h>

#define B 8
#define N 2048
#define C 128
#define F 128
#define GALPHA 0.2f
#define NCH 64
#define CH 32    /* N / NCH */

__device__ float g_h[B*N*F];
__device__ float g_e1[B*N], g_e2[B*N];
__device__ float g_P1[B*N], g_N1[B*N];
__device__ int   g_perm[B*N];
__device__ float g_sp2[B*N], g_sn2[B*N];   // sorted exp(e2), exp(0.2*e2)
__device__ float g_ctP[B*NCH*F];           // vector chunk totals
__device__ float g_ctN[B*NCH*F];
__device__ float g_SP[B*(N+1)*F];          // full exclusive prefix of P2*h (sorted)
__device__ float g_SN[B*(N+1)*F];
__device__ float g_sP[B*(N+1)];            // scalar exclusive prefixes
__device__ float g_sN[B*(N+1)];
__device__ int   g_kk[B*N];                // per-row threshold index
__device__ int   g_flag1[B*NCH];           // chunk totals published

// ---------------------------------------------------------------------------
// Kernel 1: h = text @ W.  128 blocks x 256 thr (32tx x 8ty), thread tile
// 16 rows x 4 cols. Fused e1/e2 + exp tables epilogue.
// ---------------------------------------------------------------------------
__global__ __launch_bounds__(256) void k_gemm_h(const float* __restrict__ text,
                                                const float* __restrict__ W,
                                                const float* __restrict__ a) {
    __shared__ float a_sh[128][33];
    __shared__ float W_sh[32][128];
    __shared__ float avec[2 * F];

    int t = threadIdx.x;
    int row0 = blockIdx.x * 128;
    if (t < 64) ((float4*)avec)[t] = ((const float4*)a)[t];

    int tx = t & 31;
    int ty = t >> 5;

    float acc[16][4];
#pragma unroll
    for (int r = 0; r < 16; ++r)
#pragma unroll
        for (int c = 0; c < 4; ++c) acc[r][c] = 0.f;

    for (int k0 = 0; k0 < C; k0 += 32) {
#pragma unroll
        for (int i = 0; i < 4; ++i) {
            int idx = t + i * 256;
            int r = idx >> 3, c4 = idx & 7;
            float4 v = *(const float4*)(text + (size_t)(row0 + r) * C + k0 + c4 * 4);
            a_sh[r][c4 * 4 + 0] = v.x;
            a_sh[r][c4 * 4 + 1] = v.y;
            a_sh[r][c4 * 4 + 2] = v.z;
            a_sh[r][c4 * 4 + 3] = v.w;
        }
#pragma unroll
        for (int i = 0; i < 4; ++i) {
            int idx = t + i * 256;
            int kr = idx >> 5, f4 = idx & 31;
            *(float4*)&W_sh[kr][f4 * 4] =
                *(const float4*)(W + (size_t)(k0 + kr) * F + f4 * 4);
        }
        __syncthreads();

#pragma unroll 8
        for (int k = 0; k < 32; ++k) {
            float4 w4 = *(const float4*)&W_sh[k][tx * 4];
#pragma unroll
            for (int r = 0; r < 16; ++r) {
                float av = a_sh[ty * 16 + r][k];
                acc[r][0] = fmaf(av, w4.x, acc[r][0]);
                acc[r][1] = fmaf(av, w4.y, acc[r][1]);
                acc[r][2] = fmaf(av, w4.z, acc[r][2]);
                acc[r][3] = fmaf(av, w4.w, acc[r][3]);
            }
        }
        __syncthreads();
    }

#pragma unroll
    for (int r = 0; r < 16; ++r) {
        int row = row0 + ty * 16 + r;
        size_t gi = (size_t)row * F + tx * 4;
        float4 o = {acc[r][0], acc[r][1], acc[r][2], acc[r][3]};
        *(float4*)(g_h + gi) = o;

        float p1 = 0.f, p2 = 0.f;
#pragma unroll
        for (int c = 0; c < 4; ++c) {
            p1 = fmaf(acc[r][c], avec[tx * 4 + c], p1);
            p2 = fmaf(acc[r][c], avec[F + tx * 4 + c], p2);
        }
#pragma unroll
        for (int o2 = 16; o2 > 0; o2 >>= 1) {
            p1 += __shfl_xor_sync(0xffffffffu, p1, o2);
            p2 += __shfl_xor_sync(0xffffffffu, p2, o2);
        }
        if (tx == 0) {
            g_e1[row] = p1;
            g_e2[row] = p2;
            g_P1[row] = expf(p1);
            g_N1[row] = expf(GALPHA * p1);
        }
    }
}

// ---------------------------------------------------------------------------
// Kernel 2: per-batch bitonic sort of (-e2) ascending with index payload.
// Epilogue: sorted exp tables, scalar prefix scans, threshold idx, flag reset.
// ---------------------------------------------------------------------------
__global__ __launch_bounds__(1024) void k_sort() {
    __shared__ float key[N];
    __shared__ int   sid[N];
    __shared__ float s1[N], s2[N];
    int b = blockIdx.x, t = threadIdx.x;

    if (t < NCH) g_flag1[b * NCH + t] = 0;   // reset before k_scanall (stream-ordered)

    for (int j = t; j < N; j += 1024) { key[j] = -g_e2[b * N + j]; sid[j] = j; }
    __syncthreads();

    for (int k2 = 2; k2 <= N; k2 <<= 1) {
        for (int j2 = k2 >> 1; j2 > 0; j2 >>= 1) {
            for (int tt = t; tt < N; tt += 1024) {
                int ixj = tt ^ j2;
                if (ixj > tt) {
                    bool up = ((tt & k2) == 0);
                    float ka = key[tt], kb = key[ixj];
                    if ((ka > kb) == up) {
                        key[tt] = kb; key[ixj] = ka;
                        int tmp = sid[tt]; sid[tt] = sid[ixj]; sid[ixj] = tmp;
                    }
                }
            }
            __syncthreads();
        }
    }

    int j0 = t, j1 = t + 1024;
    float p20 = expf(-key[j0]), p21 = expf(-key[j1]);
    float n20 = expf(-GALPHA * key[j0]), n21 = expf(-GALPHA * key[j1]);
    g_perm[b * N + j0] = sid[j0];  g_perm[b * N + j1] = sid[j1];
    g_sp2[b * N + j0] = p20;       g_sp2[b * N + j1] = p21;
    g_sn2[b * N + j0] = n20;       g_sn2[b * N + j1] = n21;
    s1[j0] = p20; s1[j1] = p21;
    s2[j0] = n20; s2[j1] = n21;
    __syncthreads();

#pragma unroll
    for (int off = 1; off < N; off <<= 1) {
        float a0 = 0.f, a1 = 0.f, c0 = 0.f, c1 = 0.f;
        if (j0 >= off) { a0 = s1[j0 - off]; c0 = s2[j0 - off]; }
        if (j1 >= off) { a1 = s1[j1 - off]; c1 = s2[j1 - off]; }
        __syncthreads();
        s1[j0] += a0; s2[j0] += c0;
        s1[j1] += a1; s2[j1] += c1;
        __syncthreads();
    }
    size_t o = (size_t)b * (N + 1);
    g_sP[o + j0] = s1[j0] - p20;  g_sP[o + j1] = s1[j1] - p21;
    g_sN[o + j0] = s2[j0] - n20;  g_sN[o + j1] = s2[j1] - n21;
    if (t == 1023) { g_sP[o + N] = s1[N - 1]; g_sN[o + N] = s2[N - 1]; }

    for (int row = t; row < N; row += 1024) {
        float e1 = g_e1[b * N + row];
        int lo = 0, hi = N;
        while (lo < hi) {
            int m = (lo + hi) >> 1;
            if (key[m] < e1) lo = m + 1; else hi = m;
        }
        g_kk[b * N + row] = lo;
    }
}

// ---------------------------------------------------------------------------
// Kernel 3: fused chunk totals + predecessor-flag lookback + prefix write.
// One h gather per chunk (kept in registers). grid (NCH, B), 128 threads.
// ---------------------------------------------------------------------------
__global__ __launch_bounds__(128) void k_scanall() {
    int c = blockIdx.x, b = blockIdx.y, f = threadIdx.x;
    int jb = b * N + c * CH;

    int rw[CH];
#pragma unroll
    for (int jj = 0; jj < CH; ++jj) rw[jj] = g_perm[jb + jj];
    float hv[CH];
#pragma unroll
    for (int jj = 0; jj < CH; ++jj)
        hv[jj] = g_h[((size_t)(b * N + rw[jj])) * F + f];

    // chunk totals
    float tp = 0.f, tn = 0.f;
#pragma unroll
    for (int jj = 0; jj < CH; ++jj) {
        tp = fmaf(g_sp2[jb + jj], hv[jj], tp);
        tn = fmaf(g_sn2[jb + jj], hv[jj], tn);
    }
    size_t ob = ((size_t)(b * NCH + c)) * F + f;
    g_ctP[ob] = tp;
    g_ctN[ob] = tn;
    __threadfence();
    __syncthreads();
    if (f == 0) atomicExch(&g_flag1[b * NCH + c], 1);

    // wait for predecessor chunk totals only
    if (c > 0) {
        volatile int* fl = g_flag1 + b * NCH;
        for (;;) {
            int ok = 1;
            if (f < c) ok = fl[f];
            if (__syncthreads_and(ok)) break;
        }
        __threadfence();
    }

    // fixed-order predicated sum of preceding totals (independent loads)
    float offP = 0.f, offN = 0.f;
    size_t ctb = ((size_t)b * NCH) * F + f;
#pragma unroll
    for (int cc = 0; cc < NCH - 1; ++cc) {
        float vp = g_ctP[ctb + (size_t)cc * F];
        float vn = g_ctN[ctb + (size_t)cc * F];
        if (cc < c) { offP += vp; offN += vn; }
    }

    // write this chunk's exclusive prefixes from registers
    float accP = offP, accN = offN;
    size_t sb = ((size_t)(b * (N + 1) + c * CH)) * F + f;
#pragma unroll
    for (int jj = 0; jj < CH; ++jj) {
        g_SP[sb + (size_t)jj * F] = accP;
        g_SN[sb + (size_t)jj * F] = accN;
        accP = fmaf(g_sp2[jb + jj], hv[jj], accP);
        accN = fmaf(g_sn2[jb + jj], hv[jj], accN);
    }
    if (c == NCH - 1) {
        g_SP[((size_t)(b * (N + 1) + N)) * F + f] = accP;
        g_SN[((size_t)(b * (N + 1) + N)) * F + f] = accN;
    }
}

// ---------------------------------------------------------------------------
// Kernel 4: per-row O(1) lookup + elu epilogue
// ---------------------------------------------------------------------------
__global__ __launch_bounds__(128) void k_out(float* __restrict__ out) {
    __shared__ int   kk[32];
    __shared__ float p1s[32], n1s[32], sps[32], sns[32];

    int t = threadIdx.x;
    int b = blockIdx.y;
    int i0 = blockIdx.x * 32;

    if (t < 32) {
        int i = b * N + i0 + t;
        int k = g_kk[i];
        kk[t] = k;
        p1s[t] = g_P1[i];
        n1s[t] = g_N1[i];
        sps[t] = g_sP[(size_t)b * (N + 1) + k];
        sns[t] = g_sN[(size_t)b * (N + 1) + k];
    }
    __syncthreads();

    float totNf = g_SN[((size_t)(b * (N + 1) + N)) * F + t];
    float totNs = g_sN[(size_t)b * (N + 1) + N];

#pragma unroll 4
    for (int r = 0; r < 32; ++r) {
        int k = kk[r];
        size_t sb = ((size_t)(b * (N + 1) + k)) * F + t;
        float SPf = g_SP[sb];
        float SNf = g_SN[sb];

        float P1 = p1s[r], N1v = n1s[r];
        float den = fmaf(P1, sps[r], N1v * (totNs - sns[r]));
        float num = fmaf(P1, SPf, N1v * (totNf - SNf));
        float hv_i = g_h[((size_t)(b * N + i0 + r)) * F + t];
        float x = num / den + GALPHA * hv_i;
        out[((size_t)(b * N + i0 + r)) * F + t] = (x > 0.f) ? x : expm1f(x);
    }
}

extern "C" void kernel_launch(void* const* d_in, const int* in_sizes, int n_in,
                              void* d_out, int out_size) {
    const float* text = (const float*)d_in[0];
    // d_in[1] = adj : unused by the reference computation
    const float* W = (const float*)d_in[2];
    const float* a = (const float*)d_in[3];
    float* out = (float*)d_out;

    k_gemm_h<<<(B * N) / 128, 256>>>(text, W, a);
    k_sort<<<B, 1024>>>();
    dim3 gsa(NCH, B);
    k_scanall<<<gsa, 128>>>();
    dim3 go(N / 32, B);
    k_out<<<go, 128>>>(out);
}

// round 15
// speedup vs baseline: 1.0844x; 1.0844x over previous
#include <cuda_runtime.h>
#include <math.h>

#define B 8
#define N 2048
#define C 128
#define F 128
#define GALPHA 0.2f
#define NCH 64
#define CH 32    /* N / NCH */

__device__ float g_h[B*N*F];
__device__ float g_e1[B*N], g_e2[B*N];
__device__ float g_P1[B*N], g_N1[B*N];
__device__ int   g_perm[B*N];
__device__ float g_sp2[B*N], g_sn2[B*N];   // sorted exp(e2), exp(0.2*e2)
__device__ float g_ctP[B*NCH*F];           // vector chunk totals
__device__ float g_ctN[B*NCH*F];
__device__ float g_SP[B*(N+1)*F];          // full exclusive prefix of P2*h (sorted)
__device__ float g_SN[B*(N+1)*F];
__device__ float g_sP[B*(N+1)];            // scalar exclusive prefixes
__device__ float g_sN[B*(N+1)];
__device__ int   g_kk[B*N];                // per-row threshold index
__device__ int   g_flag1[B*NCH];           // chunk totals published

// ---------------------------------------------------------------------------
// Kernel 1: h = text @ W.  128 blocks x 256 thr (32tx x 8ty), thread tile
// 16 rows x 4 cols. Fused e1/e2 + exp tables epilogue.
// ---------------------------------------------------------------------------
__global__ __launch_bounds__(256) void k_gemm_h(const float* __restrict__ text,
                                                const float* __restrict__ W,
                                                const float* __restrict__ a) {
    __shared__ float a_sh[128][33];
    __shared__ float W_sh[32][128];
    __shared__ float avec[2 * F];

    int t = threadIdx.x;
    int row0 = blockIdx.x * 128;
    if (t < 64) ((float4*)avec)[t] = ((const float4*)a)[t];

    int tx = t & 31;
    int ty = t >> 5;

    float acc[16][4];
#pragma unroll
    for (int r = 0; r < 16; ++r)
#pragma unroll
        for (int c = 0; c < 4; ++c) acc[r][c] = 0.f;

    for (int k0 = 0; k0 < C; k0 += 32) {
#pragma unroll
        for (int i = 0; i < 4; ++i) {
            int idx = t + i * 256;
            int r = idx >> 3, c4 = idx & 7;
            float4 v = *(const float4*)(text + (size_t)(row0 + r) * C + k0 + c4 * 4);
            a_sh[r][c4 * 4 + 0] = v.x;
            a_sh[r][c4 * 4 + 1] = v.y;
            a_sh[r][c4 * 4 + 2] = v.z;
            a_sh[r][c4 * 4 + 3] = v.w;
        }
#pragma unroll
        for (int i = 0; i < 4; ++i) {
            int idx = t + i * 256;
            int kr = idx >> 5, f4 = idx & 31;
            *(float4*)&W_sh[kr][f4 * 4] =
                *(const float4*)(W + (size_t)(k0 + kr) * F + f4 * 4);
        }
        __syncthreads();

#pragma unroll 8
        for (int k = 0; k < 32; ++k) {
            float4 w4 = *(const float4*)&W_sh[k][tx * 4];
#pragma unroll
            for (int r = 0; r < 16; ++r) {
                float av = a_sh[ty * 16 + r][k];
                acc[r][0] = fmaf(av, w4.x, acc[r][0]);
                acc[r][1] = fmaf(av, w4.y, acc[r][1]);
                acc[r][2] = fmaf(av, w4.z, acc[r][2]);
                acc[r][3] = fmaf(av, w4.w, acc[r][3]);
            }
        }
        __syncthreads();
    }

#pragma unroll
    for (int r = 0; r < 16; ++r) {
        int row = row0 + ty * 16 + r;
        size_t gi = (size_t)row * F + tx * 4;
        float4 o = {acc[r][0], acc[r][1], acc[r][2], acc[r][3]};
        *(float4*)(g_h + gi) = o;

        float p1 = 0.f, p2 = 0.f;
#pragma unroll
        for (int c = 0; c < 4; ++c) {
            p1 = fmaf(acc[r][c], avec[tx * 4 + c], p1);
            p2 = fmaf(acc[r][c], avec[F + tx * 4 + c], p2);
        }
#pragma unroll
        for (int o2 = 16; o2 > 0; o2 >>= 1) {
            p1 += __shfl_xor_sync(0xffffffffu, p1, o2);
            p2 += __shfl_xor_sync(0xffffffffu, p2, o2);
        }
        if (tx == 0) {
            g_e1[row] = p1;
            g_e2[row] = p2;
            g_P1[row] = expf(p1);
            g_N1[row] = expf(GALPHA * p1);
        }
    }
}

// ---------------------------------------------------------------------------
// Kernel 2: per-batch bitonic sort of (-e2) ascending with index payload.
// Epilogue: sorted exp tables, scalar prefix scans, threshold idx, flag reset.
// ---------------------------------------------------------------------------
__global__ __launch_bounds__(1024) void k_sort() {
    __shared__ float key[N];
    __shared__ int   sid[N];
    __shared__ float s1[N], s2[N];
    int b = blockIdx.x, t = threadIdx.x;

    if (t < NCH) g_flag1[b * NCH + t] = 0;   // reset before k_scanall (stream-ordered)

    for (int j = t; j < N; j += 1024) { key[j] = -g_e2[b * N + j]; sid[j] = j; }
    __syncthreads();

    for (int k2 = 2; k2 <= N; k2 <<= 1) {
        for (int j2 = k2 >> 1; j2 > 0; j2 >>= 1) {
            for (int tt = t; tt < N; tt += 1024) {
                int ixj = tt ^ j2;
                if (ixj > tt) {
                    bool up = ((tt & k2) == 0);
                    float ka = key[tt], kb = key[ixj];
                    if ((ka > kb) == up) {
                        key[tt] = kb; key[ixj] = ka;
                        int tmp = sid[tt]; sid[tt] = sid[ixj]; sid[ixj] = tmp;
                    }
                }
            }
            __syncthreads();
        }
    }

    int j0 = t, j1 = t + 1024;
    float p20 = expf(-key[j0]), p21 = expf(-key[j1]);
    float n20 = expf(-GALPHA * key[j0]), n21 = expf(-GALPHA * key[j1]);
    g_perm[b * N + j0] = sid[j0];  g_perm[b * N + j1] = sid[j1];
    g_sp2[b * N + j0] = p20;       g_sp2[b * N + j1] = p21;
    g_sn2[b * N + j0] = n20;       g_sn2[b * N + j1] = n21;
    s1[j0] = p20; s1[j1] = p21;
    s2[j0] = n20; s2[j1] = n21;
    __syncthreads();

#pragma unroll
    for (int off = 1; off < N; off <<= 1) {
        float a0 = 0.f, a1 = 0.f, c0 = 0.f, c1 = 0.f;
        if (j0 >= off) { a0 = s1[j0 - off]; c0 = s2[j0 - off]; }
        if (j1 >= off) { a1 = s1[j1 - off]; c1 = s2[j1 - off]; }
        __syncthreads();
        s1[j0] += a0; s2[j0] += c0;
        s1[j1] += a1; s2[j1] += c1;
        __syncthreads();
    }
    size_t o = (size_t)b * (N + 1);
    g_sP[o + j0] = s1[j0] - p20;  g_sP[o + j1] = s1[j1] - p21;
    g_sN[o + j0] = s2[j0] - n20;  g_sN[o + j1] = s2[j1] - n21;
    if (t == 1023) { g_sP[o + N] = s1[N - 1]; g_sN[o + N] = s2[N - 1]; }

    for (int row = t; row < N; row += 1024) {
        float e1 = g_e1[b * N + row];
        int lo = 0, hi = N;
        while (lo < hi) {
            int m = (lo + hi) >> 1;
            if (key[m] < e1) lo = m + 1; else hi = m;
        }
        g_kk[b * N + row] = lo;
    }
}

// ---------------------------------------------------------------------------
// Kernel 3: fused chunk totals + predecessor-flag lookback + prefix write.
// ---------------------------------------------------------------------------
__global__ __launch_bounds__(128) void k_scanall() {
    int c = blockIdx.x, b = blockIdx.y, f = threadIdx.x;
    int jb = b * N + c * CH;

    int rw[CH];
#pragma unroll
    for (int jj = 0; jj < CH; ++jj) rw[jj] = g_perm[jb + jj];
    float hv[CH];
#pragma unroll
    for (int jj = 0; jj < CH; ++jj)
        hv[jj] = g_h[((size_t)(b * N + rw[jj])) * F + f];

    float tp = 0.f, tn = 0.f;
#pragma unroll
    for (int jj = 0; jj < CH; ++jj) {
        tp = fmaf(g_sp2[jb + jj], hv[jj], tp);
        tn = fmaf(g_sn2[jb + jj], hv[jj], tn);
    }
    size_t ob = ((size_t)(b * NCH + c)) * F + f;
    g_ctP[ob] = tp;
    g_ctN[ob] = tn;
    __threadfence();
    __syncthreads();
    if (f == 0) atomicExch(&g_flag1[b * NCH + c], 1);

    if (c > 0) {
        volatile int* fl = g_flag1 + b * NCH;
        for (;;) {
            int ok = 1;
            if (f < c) ok = fl[f];
            if (__syncthreads_and(ok)) break;
        }
        __threadfence();
    }

    float offP = 0.f, offN = 0.f;
    size_t ctb = ((size_t)b * NCH) * F + f;
#pragma unroll
    for (int cc = 0; cc < NCH - 1; ++cc) {
        float vp = g_ctP[ctb + (size_t)cc * F];
        float vn = g_ctN[ctb + (size_t)cc * F];
        if (cc < c) { offP += vp; offN += vn; }
    }

    float accP = offP, accN = offN;
    size_t sb = ((size_t)(b * (N + 1) + c * CH)) * F + f;
#pragma unroll
    for (int jj = 0; jj < CH; ++jj) {
        g_SP[sb + (size_t)jj * F] = accP;
        g_SN[sb + (size_t)jj * F] = accN;
        accP = fmaf(g_sp2[jb + jj], hv[jj], accP);
        accN = fmaf(g_sn2[jb + jj], hv[jj], accN);
    }
    if (c == NCH - 1) {
        g_SP[((size_t)(b * (N + 1) + N)) * F + f] = accP;
        g_SN[((size_t)(b * (N + 1) + N)) * F + f] = accN;
    }
}

// ---------------------------------------------------------------------------
// Kernel 4: per-row O(1) lookup + elu epilogue.
// 256 threads: two 128-wide f-groups, each handles 16 of the 32 rows.
// ---------------------------------------------------------------------------
__global__ __launch_bounds__(256) void k_out(float* __restrict__ out) {
    __shared__ int   kk[32];
    __shared__ float p1s[32], n1s[32], sps[32], sns[32];

    int t = threadIdx.x;
    int f = t & 127;
    int half = t >> 7;          // 0 or 1: rows [0,16) or [16,32)
    int b = blockIdx.y;
    int i0 = blockIdx.x * 32;

    if (t < 32) {
        int i = b * N + i0 + t;
        int k = g_kk[i];
        kk[t] = k;
        p1s[t] = g_P1[i];
        n1s[t] = g_N1[i];
        sps[t] = g_sP[(size_t)b * (N + 1) + k];
        sns[t] = g_sN[(size_t)b * (N + 1) + k];
    }
    __syncthreads();

    float totNf = g_SN[((size_t)(b * (N + 1) + N)) * F + f];
    float totNs = g_sN[(size_t)b * (N + 1) + N];

#pragma unroll 8
    for (int rr = 0; rr < 16; ++rr) {
        int r = half * 16 + rr;
        int k = kk[r];
        size_t sb = ((size_t)(b * (N + 1) + k)) * F + f;
        float SPf = g_SP[sb];
        float SNf = g_SN[sb];

        float P1 = p1s[r], N1v = n1s[r];
        float den = fmaf(P1, sps[r], N1v * (totNs - sns[r]));
        float num = fmaf(P1, SPf, N1v * (totNf - SNf));
        float hv_i = g_h[((size_t)(b * N + i0 + r)) * F + f];
        float x = num / den + GALPHA * hv_i;
        out[((size_t)(b * N + i0 + r)) * F + f] = (x > 0.f) ? x : expm1f(x);
    }
}

extern "C" void kernel_launch(void* const* d_in, const int* in_sizes, int n_in,
                              void* d_out, int out_size) {
    const float* text = (const float*)d_in[0];
    // d_in[1] = adj : unused by the reference computation
    const float* W = (const float*)d_in[2];
    const float* a = (const float*)d_in[3];
    float* out = (float*)d_out;

    k_gemm_h<<<(B * N) / 128, 256>>>(text, W, a);
    k_sort<<<B, 1024>>>();
    dim3 gsa(NCH, B);
    k_scanall<<<gsa, 128>>>();
    dim3 go(N / 32, B);
    k_out<<<go, 256>>>(out);
}

// round 16
// speedup vs baseline: 1.1542x; 1.0644x over previous
#include <cuda_runtime.h>
#include <math.h>

#define B 8
#define N 2048
#define C 128
#define F 128
#define GALPHA 0.2f
#define NCH 64
#define CH 32    /* N / NCH */

__device__ float g_h[B*N*F];
__device__ float g_e1[B*N], g_e2[B*N];
__device__ float g_P1[B*N], g_N1[B*N];
__device__ int   g_perm[B*N];
__device__ float g_sp2[B*N], g_sn2[B*N];   // sorted exp(e2), exp(0.2*e2)
__device__ float g_ctP[B*NCH*F];           // vector chunk totals
__device__ float g_ctN[B*NCH*F];
__device__ float g_SP[B*(N+1)*F];          // full exclusive prefix of P2*h (sorted)
__device__ float g_SN[B*(N+1)*F];
__device__ float g_sP[B*(N+1)];            // scalar exclusive prefixes
__device__ float g_sN[B*(N+1)];
__device__ int   g_kk[B*N];                // per-row threshold index
__device__ int   g_flag1[B*NCH];           // chunk totals published

// ---------------------------------------------------------------------------
// Kernel 1: h = text @ W.  128 blocks x 256 thr (32tx x 8ty), thread tile
// 16 rows x 4 cols. Fused e1/e2 + exp tables epilogue.
// ---------------------------------------------------------------------------
__global__ __launch_bounds__(256) void k_gemm_h(const float* __restrict__ text,
                                                const float* __restrict__ W,
                                                const float* __restrict__ a) {
    __shared__ float a_sh[128][33];
    __shared__ float W_sh[32][128];
    __shared__ float avec[2 * F];

    int t = threadIdx.x;
    int row0 = blockIdx.x * 128;
    if (t < 64) ((float4*)avec)[t] = ((const float4*)a)[t];

    int tx = t & 31;
    int ty = t >> 5;

    float acc[16][4];
#pragma unroll
    for (int r = 0; r < 16; ++r)
#pragma unroll
        for (int c = 0; c < 4; ++c) acc[r][c] = 0.f;

    for (int k0 = 0; k0 < C; k0 += 32) {
#pragma unroll
        for (int i = 0; i < 4; ++i) {
            int idx = t + i * 256;
            int r = idx >> 3, c4 = idx & 7;
            float4 v = *(const float4*)(text + (size_t)(row0 + r) * C + k0 + c4 * 4);
            a_sh[r][c4 * 4 + 0] = v.x;
            a_sh[r][c4 * 4 + 1] = v.y;
            a_sh[r][c4 * 4 + 2] = v.z;
            a_sh[r][c4 * 4 + 3] = v.w;
        }
#pragma unroll
        for (int i = 0; i < 4; ++i) {
            int idx = t + i * 256;
            int kr = idx >> 5, f4 = idx & 31;
            *(float4*)&W_sh[kr][f4 * 4] =
                *(const float4*)(W + (size_t)(k0 + kr) * F + f4 * 4);
        }
        __syncthreads();

#pragma unroll 8
        for (int k = 0; k < 32; ++k) {
            float4 w4 = *(const float4*)&W_sh[k][tx * 4];
#pragma unroll
            for (int r = 0; r < 16; ++r) {
                float av = a_sh[ty * 16 + r][k];
                acc[r][0] = fmaf(av, w4.x, acc[r][0]);
                acc[r][1] = fmaf(av, w4.y, acc[r][1]);
                acc[r][2] = fmaf(av, w4.z, acc[r][2]);
                acc[r][3] = fmaf(av, w4.w, acc[r][3]);
            }
        }
        __syncthreads();
    }

#pragma unroll
    for (int r = 0; r < 16; ++r) {
        int row = row0 + ty * 16 + r;
        size_t gi = (size_t)row * F + tx * 4;
        float4 o = {acc[r][0], acc[r][1], acc[r][2], acc[r][3]};
        *(float4*)(g_h + gi) = o;

        float p1 = 0.f, p2 = 0.f;
#pragma unroll
        for (int c = 0; c < 4; ++c) {
            p1 = fmaf(acc[r][c], avec[tx * 4 + c], p1);
            p2 = fmaf(acc[r][c], avec[F + tx * 4 + c], p2);
        }
#pragma unroll
        for (int o2 = 16; o2 > 0; o2 >>= 1) {
            p1 += __shfl_xor_sync(0xffffffffu, p1, o2);
            p2 += __shfl_xor_sync(0xffffffffu, p2, o2);
        }
        if (tx == 0) {
            g_e1[row] = p1;
            g_e2[row] = p2;
            g_P1[row] = expf(p1);
            g_N1[row] = expf(GALPHA * p1);
        }
    }
}

// ---------------------------------------------------------------------------
// Kernel 2: per-batch bitonic sort of (-e2) ascending with index payload.
// Epilogue: sorted exp tables, scalar prefix scans, threshold idx, flag reset.
// ---------------------------------------------------------------------------
__global__ __launch_bounds__(1024) void k_sort() {
    __shared__ float key[N];
    __shared__ int   sid[N];
    __shared__ float s1[N], s2[N];
    int b = blockIdx.x, t = threadIdx.x;

    if (t < NCH) g_flag1[b * NCH + t] = 0;   // reset before k_scanall (stream-ordered)

    for (int j = t; j < N; j += 1024) { key[j] = -g_e2[b * N + j]; sid[j] = j; }
    __syncthreads();

    for (int k2 = 2; k2 <= N; k2 <<= 1) {
        for (int j2 = k2 >> 1; j2 > 0; j2 >>= 1) {
            for (int tt = t; tt < N; tt += 1024) {
                int ixj = tt ^ j2;
                if (ixj > tt) {
                    bool up = ((tt & k2) == 0);
                    float ka = key[tt], kb = key[ixj];
                    if ((ka > kb) == up) {
                        key[tt] = kb; key[ixj] = ka;
                        int tmp = sid[tt]; sid[tt] = sid[ixj]; sid[ixj] = tmp;
                    }
                }
            }
            __syncthreads();
        }
    }

    int j0 = t, j1 = t + 1024;
    float p20 = expf(-key[j0]), p21 = expf(-key[j1]);
    float n20 = expf(-GALPHA * key[j0]), n21 = expf(-GALPHA * key[j1]);
    g_perm[b * N + j0] = sid[j0];  g_perm[b * N + j1] = sid[j1];
    g_sp2[b * N + j0] = p20;       g_sp2[b * N + j1] = p21;
    g_sn2[b * N + j0] = n20;       g_sn2[b * N + j1] = n21;
    s1[j0] = p20; s1[j1] = p21;
    s2[j0] = n20; s2[j1] = n21;
    __syncthreads();

#pragma unroll
    for (int off = 1; off < N; off <<= 1) {
        float a0 = 0.f, a1 = 0.f, c0 = 0.f, c1 = 0.f;
        if (j0 >= off) { a0 = s1[j0 - off]; c0 = s2[j0 - off]; }
        if (j1 >= off) { a1 = s1[j1 - off]; c1 = s2[j1 - off]; }
        __syncthreads();
        s1[j0] += a0; s2[j0] += c0;
        s1[j1] += a1; s2[j1] += c1;
        __syncthreads();
    }
    size_t o = (size_t)b * (N + 1);
    g_sP[o + j0] = s1[j0] - p20;  g_sP[o + j1] = s1[j1] - p21;
    g_sN[o + j0] = s2[j0] - n20;  g_sN[o + j1] = s2[j1] - n21;
    if (t == 1023) { g_sP[o + N] = s1[N - 1]; g_sN[o + N] = s2[N - 1]; }

    for (int row = t; row < N; row += 1024) {
        float e1 = g_e1[b * N + row];
        int lo = 0, hi = N;
        while (lo < hi) {
            int m = (lo + hi) >> 1;
            if (key[m] < e1) lo = m + 1; else hi = m;
        }
        g_kk[b * N + row] = lo;
    }
}

// ---------------------------------------------------------------------------
// Kernel 3: fused chunk totals + predecessor-flag lookback + prefix write.
// ---------------------------------------------------------------------------
__global__ __launch_bounds__(128) void k_scanall() {
    int c = blockIdx.x, b = blockIdx.y, f = threadIdx.x;
    int jb = b * N + c * CH;

    int rw[CH];
#pragma unroll
    for (int jj = 0; jj < CH; ++jj) rw[jj] = g_perm[jb + jj];
    float hv[CH];
#pragma unroll
    for (int jj = 0; jj < CH; ++jj)
        hv[jj] = g_h[((size_t)(b * N + rw[jj])) * F + f];

    float tp = 0.f, tn = 0.f;
#pragma unroll
    for (int jj = 0; jj < CH; ++jj) {
        tp = fmaf(g_sp2[jb + jj], hv[jj], tp);
        tn = fmaf(g_sn2[jb + jj], hv[jj], tn);
    }
    size_t ob = ((size_t)(b * NCH + c)) * F + f;
    g_ctP[ob] = tp;
    g_ctN[ob] = tn;
    __threadfence();
    __syncthreads();
    if (f == 0) atomicExch(&g_flag1[b * NCH + c], 1);

    if (c > 0) {
        volatile int* fl = g_flag1 + b * NCH;
        for (;;) {
            int ok = 1;
            if (f < c) ok = fl[f];
            if (__syncthreads_and(ok)) break;
        }
        __threadfence();
    }

    float offP = 0.f, offN = 0.f;
    size_t ctb = ((size_t)b * NCH) * F + f;
#pragma unroll
    for (int cc = 0; cc < NCH - 1; ++cc) {
        float vp = g_ctP[ctb + (size_t)cc * F];
        float vn = g_ctN[ctb + (size_t)cc * F];
        if (cc < c) { offP += vp; offN += vn; }
    }

    float accP = offP, accN = offN;
    size_t sb = ((size_t)(b * (N + 1) + c * CH)) * F + f;
#pragma unroll
    for (int jj = 0; jj < CH; ++jj) {
        g_SP[sb + (size_t)jj * F] = accP;
        g_SN[sb + (size_t)jj * F] = accN;
        accP = fmaf(g_sp2[jb + jj], hv[jj], accP);
        accN = fmaf(g_sn2[jb + jj], hv[jj], accN);
    }
    if (c == NCH - 1) {
        g_SP[((size_t)(b * (N + 1) + N)) * F + f] = accP;
        g_SN[((size_t)(b * (N + 1) + N)) * F + f] = accN;
    }
}

// ---------------------------------------------------------------------------
// Kernel 4: per-row O(1) lookup + elu epilogue. float4 over f.
// 256 threads = 8 groups of 32 lanes; each group handles 4 of 32 rows.
// ---------------------------------------------------------------------------
__global__ __launch_bounds__(256) void k_out(float* __restrict__ out) {
    __shared__ int   kk[32];
    __shared__ float p1s[32], n1s[32], sps[32], sns[32];

    int t = threadIdx.x;
    int lane = t & 31;          // float4 index: covers f = lane*4 .. lane*4+3
    int grp = t >> 5;           // 8 groups; group g handles rows g*4 .. g*4+3
    int b = blockIdx.y;
    int i0 = blockIdx.x * 32;

    if (t < 32) {
        int i = b * N + i0 + t;
        int k = g_kk[i];
        kk[t] = k;
        p1s[t] = g_P1[i];
        n1s[t] = g_N1[i];
        sps[t] = g_sP[(size_t)b * (N + 1) + k];
        sns[t] = g_sN[(size_t)b * (N + 1) + k];
    }
    __syncthreads();

    float4 totNf = *(const float4*)(g_SN + ((size_t)(b * (N + 1) + N)) * F + lane * 4);
    float totNs = g_sN[(size_t)b * (N + 1) + N];

#pragma unroll
    for (int rr = 0; rr < 4; ++rr) {
        int r = grp * 4 + rr;
        int k = kk[r];
        size_t sb = ((size_t)(b * (N + 1) + k)) * F + lane * 4;
        float4 SPf = *(const float4*)(g_SP + sb);
        float4 SNf = *(const float4*)(g_SN + sb);

        float P1 = p1s[r], N1v = n1s[r];
        float den = fmaf(P1, sps[r], N1v * (totNs - sns[r]));
        float dinv = 1.f / den;

        size_t hb = ((size_t)(b * N + i0 + r)) * F + lane * 4;
        float4 hv = *(const float4*)(g_h + hb);

        float4 o;
        {
            float num = fmaf(P1, SPf.x, N1v * (totNf.x - SNf.x));
            float x = num * dinv + GALPHA * hv.x;
            o.x = (x > 0.f) ? x : expm1f(x);
            num = fmaf(P1, SPf.y, N1v * (totNf.y - SNf.y));
            x = num * dinv + GALPHA * hv.y;
            o.y = (x > 0.f) ? x : expm1f(x);
            num = fmaf(P1, SPf.z, N1v * (totNf.z - SNf.z));
            x = num * dinv + GALPHA * hv.z;
            o.z = (x > 0.f) ? x : expm1f(x);
            num = fmaf(P1, SPf.w, N1v * (totNf.w - SNf.w));
            x = num * dinv + GALPHA * hv.w;
            o.w = (x > 0.f) ? x : expm1f(x);
        }
        *(float4*)(out + hb) = o;
    }
}

extern "C" void kernel_launch(void* const* d_in, const int* in_sizes, int n_in,
                              void* d_out, int out_size) {
    const float* text = (const float*)d_in[0];
    // d_in[1] = adj : unused by the reference computation
    const float* W = (const float*)d_in[2];
    const float* a = (const float*)d_in[3];
    float* out = (float*)d_out;

    k_gemm_h<<<(B * N) / 128, 256>>>(text, W, a);
    k_sort<<<B, 1024>>>();
    dim3 gsa(NCH, B);
    k_scanall<<<gsa, 128>>>();
    dim3 go(N / 32, B);
    k_out<<<go, 256>>>(out);
}